// round 4
// baseline (speedup 1.0000x reference)
#include <cuda_runtime.h>
#include <cuda_bf16.h>
#include <math.h>
#include <stdint.h>

// ---------------------------------------------------------------------------
// Problem constants
// ---------------------------------------------------------------------------
constexpr int NN  = 30000;    // nodes per type
constexpr int NE  = 400000;   // edges per relation
constexpr int NR  = 10;       // relations
constexpr int NT  = 4;        // node types
constexpr int C1  = 128;      // layer1 channels
constexpr int H1  = 8;        // layer1 heads
constexpr int IN1 = 256;      // layer1 input dim
constexpr int C2  = 32;       // layer2 channels

__constant__ int c_SRC[NR]    = {0,1,2,3,0,1,2,1,3,1};
__constant__ int c_DST[NR]    = {0,1,2,3,1,0,1,2,1,3};
__constant__ int c_GRPOFF[5]  = {0,2,6,8,10};
__constant__ int c_GRP[NR]    = {0,5, 1,4,6,8, 2,7, 3,9};

// ---------------------------------------------------------------------------
// Scratch (static device arrays: allocation-free)
// ---------------------------------------------------------------------------
__device__ __align__(16) float g_h1   [NT*NN*C1];
__device__ __align__(16) float g_asrc1[NR*NN*H1];
__device__ __align__(16) float g_adst1[NR*NN*H1];
__device__ __align__(16) float g_out1 [NR*NN*C1];
__device__ __align__(16) float g_x2   [NT*NN*C1];
__device__ __align__(16) float g_h2   [NT*NN*C2];
__device__ __align__(16) float g_asrc2[NR*NN];
__device__ __align__(16) float g_adst2[NR*NN];
__device__ __align__(16) float g_out2 [NR*NN*C2];
__device__ float g_colsum1[NR*C1];
__device__ float g_colsum2[NR*C2];
__device__ float g_sattn1[NR];
__device__ float g_sattn2[NR];
__device__ int   g_counts [NR*NN];
__device__ int   g_offsets[NR*(NN+1)];
__device__ int   g_cursor [NR*NN];
__device__ int   g_srcs   [NR*NE];
__device__ __align__(16) float g_w1[(long)NR*NE*H1];
__device__ __align__(16) float g_w2[NR*NE];

// Converted (transposed, bf16 hi/lo) weights: [n][k] layout, k contiguous
constexpr int OFF_P1 = 0;                       // 4 x 256 x 128
constexpr int OFF_K1 = OFF_P1 + 4*IN1*C1;       // 128 x 128
constexpr int OFF_P2 = OFF_K1 + C1*C1;          // 4 x 128 x 32
constexpr int OFF_K2 = OFF_P2 + 4*C1*C2;        // 32 x 32
constexpr int W_TOTAL = OFF_K2 + C2*C2;
__device__ __align__(16) __nv_bfloat16 g_whi[W_TOTAL];
__device__ __align__(16) __nv_bfloat16 g_wlo[W_TOTAL];

// ---------------------------------------------------------------------------
// Zeroing (counts + colsums)
// ---------------------------------------------------------------------------
__global__ void k_zero() {
    int i = blockIdx.x * blockDim.x + threadIdx.x;
    if (i < NR*NN) g_counts[i] = 0;
    if (i < NR*C1) g_colsum1[i] = 0.f;
    if (i < NR*C2) g_colsum2[i] = 0.f;
}

// ---------------------------------------------------------------------------
// Weight conversion: W[K][N] fp32 row-major -> hi/lo bf16 [N][K] (k contiguous)
// ---------------------------------------------------------------------------
__global__ void k_convW(const float* __restrict__ W,
                        __nv_bfloat16* __restrict__ hi,
                        __nv_bfloat16* __restrict__ lo,
                        int K, int N)
{
    int z = blockIdx.z;
    W  += (long)z * K * N;
    hi += (long)z * K * N;
    lo += (long)z * K * N;
    int idx = blockIdx.x * blockDim.x + threadIdx.x;
    if (idx >= K*N) return;
    int k = idx / N, n = idx - k*N;
    float x = W[idx];
    __nv_bfloat16 h = __float2bfloat16(x);
    hi[n*K + k] = h;
    lo[n*K + k] = __float2bfloat16(x - __bfloat162float(h));
}

// ---------------------------------------------------------------------------
// CSR build by destination (shared by both layers)
// ---------------------------------------------------------------------------
__global__ void k_count(const int* __restrict__ edges) {
    int idx = blockIdx.x * blockDim.x + threadIdx.x;
    if (idx >= NR*NE) return;
    int e = idx / NE, i = idx - e*NE;
    int col = edges[e*2*NE + NE + i];
    atomicAdd(&g_counts[e*NN + col], 1);
}

__global__ void k_scan() {   // one block (1024 threads) per relation
    const int e = blockIdx.x;
    const int t = threadIdx.x;
    constexpr int CH = 30;
    int base = t * CH;
    int cnt[CH];
    int sum = 0;
#pragma unroll
    for (int i = 0; i < CH; i++) {
        int idx = base + i;
        int v = (idx < NN) ? g_counts[e*NN + idx] : 0;
        cnt[i] = v; sum += v;
    }
    __shared__ int s[1024];
    s[t] = sum; __syncthreads();
    for (int d = 1; d < 1024; d <<= 1) {
        int v = (t >= d) ? s[t-d] : 0;
        __syncthreads();
        s[t] += v;
        __syncthreads();
    }
    int run = s[t] - sum;
#pragma unroll
    for (int i = 0; i < CH; i++) {
        int idx = base + i;
        if (idx < NN) {
            g_offsets[e*(NN+1) + idx] = run;
            g_cursor [e*NN + idx]     = run;
            run += cnt[i];
        }
    }
    if (t == 1023) g_offsets[e*(NN+1) + NN] = s[1023];
}

__global__ void k_fill(const int* __restrict__ edges) {
    int idx = blockIdx.x * blockDim.x + threadIdx.x;
    if (idx >= NR*NE) return;
    int e = idx / NE, i = idx - e*NE;
    int row = edges[e*2*NE + i];
    int col = edges[e*2*NE + NE + i];
    int pos = atomicAdd(&g_cursor[e*NN + col], 1);
    g_srcs[e*NE + pos] = row;
}

// ---------------------------------------------------------------------------
// Tensor-core GEMM: C[M x BN] = A[M x K] @ B[K x BN] (+bias)
// A fp32 in gmem (converted to bf16 hi/lo in-kernel); B preconverted bf16
// hi/lo [n][k]. mma.sync.m16n8k16 bf16, fp32 accum.
// SPLIT: 3-term bf16 emulated fp32 (hi*hi + hi*lo + lo*hi).
// MODE 0: C = acc + bias.  MODE 1: colsum[col] += sum_rows tanh(acc + bias).
// ---------------------------------------------------------------------------
__device__ __forceinline__ void mma16816(float* c, uint32_t a0, uint32_t a1,
                                         uint32_t a2, uint32_t a3,
                                         uint32_t b0, uint32_t b1)
{
    asm volatile(
        "mma.sync.aligned.m16n8k16.row.col.f32.bf16.bf16.f32 "
        "{%0,%1,%2,%3}, {%4,%5,%6,%7}, {%8,%9}, {%0,%1,%2,%3};"
        : "+f"(c[0]), "+f"(c[1]), "+f"(c[2]), "+f"(c[3])
        : "r"(a0), "r"(a1), "r"(a2), "r"(a3), "r"(b0), "r"(b1));
}

template <int BN, bool SPLIT, int MODE>
__global__ void __launch_bounds__(256)
k_tmma(const float* __restrict__ A,
       const __nv_bfloat16* __restrict__ Bhi,
       const __nv_bfloat16* __restrict__ Blo,
       const float* __restrict__ bias, float* __restrict__ C,
       int M, int K, long strideA, long strideB, long strideBias, long strideC,
       float* __restrict__ colsum, int colsumStride)
{
    constexpr int BM  = 128;
    constexpr int BK  = 32;
    constexpr int STR = BK + 8;                 // padded row (conflict-free frags)
    constexpr int NWN = (BN == 128) ? 2 : 1;    // warps along n
    constexpr int NWM = 8 / NWN;                // warps along m
    constexpr int WMT = BM / (16 * NWM);        // m16 tiles per warp
    constexpr int WNT = BN / (8 * NWN);         // n8 tiles per warp

    __shared__ __nv_bfloat16 Ah[BM * STR];
    __shared__ __nv_bfloat16 Bh[BN * STR];
    __shared__ __nv_bfloat16 Al[SPLIT ? BM * STR : 2];
    __shared__ __nv_bfloat16 Bl[SPLIT ? BN * STR : 2];
    __shared__ float cs[BN];

    const int z = blockIdx.z;
    A   += (long)z * strideA;
    Bhi += (long)z * strideB;
    if (SPLIT) Blo += (long)z * strideB;
    bias += (long)z * strideBias;
    if (MODE == 0) C += (long)z * strideC;

    const int tid  = threadIdx.x;
    const int wid  = tid >> 5, lane = tid & 31;
    const int g    = lane >> 2, tg = lane & 3;
    const int wm   = wid / NWN, wn = wid % NWN;
    const int mbase = wm * (WMT * 16);
    const int nbase = wn * (WNT * 8);
    const int m0   = blockIdx.x * BM;

    if (MODE == 1 && tid < BN) cs[tid] = 0.f;

    float acc[WMT][WNT][4];
#pragma unroll
    for (int i = 0; i < WMT; i++)
#pragma unroll
        for (int j = 0; j < WNT; j++)
#pragma unroll
            for (int r = 0; r < 4; r++) acc[i][j][r] = 0.f;

    const int arow = tid >> 1;          // 0..127
    const int aseg = tid & 1;           // 16-float half

    for (int k0 = 0; k0 < K; k0 += BK) {
        // ---- A tile: gmem fp32 -> smem bf16 hi/lo ----
        {
            float xv[16];
            bool valid = (m0 + arow) < M;
            if (valid) {
                const float4* src = reinterpret_cast<const float4*>(
                    A + (long)(m0 + arow)*K + k0 + aseg*16);
#pragma unroll
                for (int i = 0; i < 4; i++) {
                    float4 v = src[i];
                    xv[i*4+0] = v.x; xv[i*4+1] = v.y;
                    xv[i*4+2] = v.z; xv[i*4+3] = v.w;
                }
            } else {
#pragma unroll
                for (int i = 0; i < 16; i++) xv[i] = 0.f;
            }
            int base = arow*STR + aseg*16;
#pragma unroll
            for (int p = 0; p < 8; p++) {
                __nv_bfloat16 h0 = __float2bfloat16(xv[2*p]);
                __nv_bfloat16 h1 = __float2bfloat16(xv[2*p+1]);
                __nv_bfloat162 hh; hh.x = h0; hh.y = h1;
                *reinterpret_cast<__nv_bfloat162*>(&Ah[base + 2*p]) = hh;
                if (SPLIT) {
                    __nv_bfloat162 ll;
                    ll.x = __float2bfloat16(xv[2*p]   - __bfloat162float(h0));
                    ll.y = __float2bfloat16(xv[2*p+1] - __bfloat162float(h1));
                    *reinterpret_cast<__nv_bfloat162*>(&Al[base + 2*p]) = ll;
                }
            }
        }
        // ---- B tile: preconverted bf16 [n][k] -> smem ----
        if (BN == 128 || tid < 2*BN) {
            int brow = tid >> 1, bseg = tid & 1;
            const uint4* src = reinterpret_cast<const uint4*>(
                Bhi + (long)brow*K + k0 + bseg*16);
            uint4* dst = reinterpret_cast<uint4*>(&Bh[brow*STR + bseg*16]);
            dst[0] = src[0]; dst[1] = src[1];
            if (SPLIT) {
                const uint4* srcl = reinterpret_cast<const uint4*>(
                    Blo + (long)brow*K + k0 + bseg*16);
                uint4* dstl = reinterpret_cast<uint4*>(&Bl[brow*STR + bseg*16]);
                dstl[0] = srcl[0]; dstl[1] = srcl[1];
            }
        }
        __syncthreads();

#pragma unroll
        for (int kk = 0; kk < BK; kk += 16) {
            uint32_t ah[WMT][4], al[WMT][4];
#pragma unroll
            for (int mt = 0; mt < WMT; mt++) {
                int base = (mbase + mt*16 + g)*STR + kk + tg*2;
                ah[mt][0] = *reinterpret_cast<const uint32_t*>(&Ah[base]);
                ah[mt][1] = *reinterpret_cast<const uint32_t*>(&Ah[base + 8*STR]);
                ah[mt][2] = *reinterpret_cast<const uint32_t*>(&Ah[base + 8]);
                ah[mt][3] = *reinterpret_cast<const uint32_t*>(&Ah[base + 8*STR + 8]);
                if (SPLIT) {
                    al[mt][0] = *reinterpret_cast<const uint32_t*>(&Al[base]);
                    al[mt][1] = *reinterpret_cast<const uint32_t*>(&Al[base + 8*STR]);
                    al[mt][2] = *reinterpret_cast<const uint32_t*>(&Al[base + 8]);
                    al[mt][3] = *reinterpret_cast<const uint32_t*>(&Al[base + 8*STR + 8]);
                }
            }
#pragma unroll
            for (int nt = 0; nt < WNT; nt++) {
                int nb = (nbase + nt*8 + g)*STR + kk + tg*2;
                uint32_t bh0 = *reinterpret_cast<const uint32_t*>(&Bh[nb]);
                uint32_t bh1 = *reinterpret_cast<const uint32_t*>(&Bh[nb + 8]);
                uint32_t bl0 = 0, bl1 = 0;
                if (SPLIT) {
                    bl0 = *reinterpret_cast<const uint32_t*>(&Bl[nb]);
                    bl1 = *reinterpret_cast<const uint32_t*>(&Bl[nb + 8]);
                }
#pragma unroll
                for (int mt = 0; mt < WMT; mt++) {
                    mma16816(acc[mt][nt], ah[mt][0], ah[mt][1], ah[mt][2], ah[mt][3], bh0, bh1);
                    if (SPLIT) {
                        mma16816(acc[mt][nt], ah[mt][0], ah[mt][1], ah[mt][2], ah[mt][3], bl0, bl1);
                        mma16816(acc[mt][nt], al[mt][0], al[mt][1], al[mt][2], al[mt][3], bh0, bh1);
                    }
                }
            }
        }
        __syncthreads();
    }

    if (MODE == 0) {
#pragma unroll
        for (int mt = 0; mt < WMT; mt++) {
            int row0 = m0 + mbase + mt*16 + g;
            int row1 = row0 + 8;
#pragma unroll
            for (int nt = 0; nt < WNT; nt++) {
                int col = nbase + nt*8 + tg*2;
                float b0 = __ldg(&bias[col]), b1 = __ldg(&bias[col+1]);
                if (row0 < M) {
                    float2 v; v.x = acc[mt][nt][0] + b0; v.y = acc[mt][nt][1] + b1;
                    *reinterpret_cast<float2*>(&C[(long)row0*BN + col]) = v;
                }
                if (row1 < M) {
                    float2 v; v.x = acc[mt][nt][2] + b0; v.y = acc[mt][nt][3] + b1;
                    *reinterpret_cast<float2*>(&C[(long)row1*BN + col]) = v;
                }
            }
        }
    } else {
#pragma unroll
        for (int nt = 0; nt < WNT; nt++) {
            int col = nbase + nt*8 + tg*2;
            float b0 = __ldg(&bias[col]), b1 = __ldg(&bias[col+1]);
            float s0 = 0.f, s1 = 0.f;
#pragma unroll
            for (int mt = 0; mt < WMT; mt++) {
                int row0 = m0 + mbase + mt*16 + g;
                if (row0 < M)     { s0 += tanhf(acc[mt][nt][0] + b0);
                                    s1 += tanhf(acc[mt][nt][1] + b1); }
                if (row0 + 8 < M) { s0 += tanhf(acc[mt][nt][2] + b0);
                                    s1 += tanhf(acc[mt][nt][3] + b1); }
            }
            atomicAdd(&cs[col], s0);
            atomicAdd(&cs[col+1], s1);
        }
        __syncthreads();
        if (tid < BN) atomicAdd(&colsum[z*colsumStride + tid], cs[tid]);
    }
}

// ---------------------------------------------------------------------------
// Attention logits, layer 1: warp per (relation, node)
// ---------------------------------------------------------------------------
__global__ void k_logits1(const float* __restrict__ att_src,
                          const float* __restrict__ att_dst)
{
    int e = blockIdx.y;
    int n = blockIdx.x * 8 + (threadIdx.x >> 5);
    if (n >= NN) return;
    int l = threadIdx.x & 31;

    const float4* hs = reinterpret_cast<const float4*>(g_h1 + c_SRC[e]*NN*C1 + n*C1);
    const float4* hd = reinterpret_cast<const float4*>(g_h1 + c_DST[e]*NN*C1 + n*C1);
    const float4* as = reinterpret_cast<const float4*>(att_src + e*C1);
    const float4* ad = reinterpret_cast<const float4*>(att_dst + e*C1);

    float4 a = hs[l], b = as[l];
    float ps = a.x*b.x + a.y*b.y + a.z*b.z + a.w*b.w;
    float4 c = hd[l], d = ad[l];
    float pd = c.x*d.x + c.y*d.y + c.z*d.z + c.w*d.w;
    ps += __shfl_xor_sync(0xffffffffu, ps, 1);
    ps += __shfl_xor_sync(0xffffffffu, ps, 2);
    pd += __shfl_xor_sync(0xffffffffu, pd, 1);
    pd += __shfl_xor_sync(0xffffffffu, pd, 2);
    if ((l & 3) == 0) {
        g_asrc1[(e*NN + n)*H1 + (l >> 2)] = ps;
        g_adst1[(e*NN + n)*H1 + (l >> 2)] = pd;
    }
}

// ---------------------------------------------------------------------------
// Segment softmax, layer 1: one warp per (relation, node)
// ---------------------------------------------------------------------------
__global__ void k_soft1() {
    int e = blockIdx.y;
    int n = blockIdx.x * 8 + (threadIdx.x >> 5);
    if (n >= NN) return;
    int l  = threadIdx.x & 31;
    int h  = l >> 2;
    int il = l & 3;

    int off = g_offsets[e*(NN+1) + n];
    int deg = g_offsets[e*(NN+1) + n + 1] - off;
    if (deg == 0) return;

    const int*   sr  = g_srcs + e*NE + off;
    const float* asr = g_asrc1 + e*NN*H1;
    float ad = g_adst1[(e*NN + n)*H1 + h];

    float m = -1e30f, s = 0.f;
    for (int i = il; i < deg; i += 4) {
        float a = asr[sr[i]*H1 + h] + ad;
        a = a > 0.f ? a : 0.2f * a;
        if (a > m) { s = s * expf(m - a) + 1.f; m = a; }
        else        s += expf(a - m);
    }
#pragma unroll
    for (int o = 1; o <= 2; o <<= 1) {
        float mo = __shfl_xor_sync(0xffffffffu, m, o);
        float so = __shfl_xor_sync(0xffffffffu, s, o);
        float mn = fmaxf(m, mo);
        s = s * expf(m - mn) + so * expf(mo - mn);
        m = mn;
    }
    float inv = 1.f / (s + 1e-16f);
    float* w = g_w1 + (long)(e*NE + off) * H1;
    for (int i = il; i < deg; i += 4) {
        float a = asr[sr[i]*H1 + h] + ad;
        a = a > 0.f ? a : 0.2f * a;
        w[i*H1 + h] = expf(a - m) * inv;
    }
}

// ---------------------------------------------------------------------------
// Aggregation layer 1: pure weighted gather
// ---------------------------------------------------------------------------
__global__ void k_agg1() {
    int e = blockIdx.y, n = blockIdx.x;
    int c = threadIdx.x;
    int h = c >> 4;
    int off = g_offsets[e*(NN+1) + n];
    int deg = g_offsets[e*(NN+1) + n + 1] - off;
    float* out = g_out1 + (long)(e*NN + n) * C1;
    if (deg == 0) { out[c] = 0.f; return; }

    const int*   sr = g_srcs + e*NE + off;
    const float* w  = g_w1 + (long)(e*NE + off) * H1;
    const float* hsrc = g_h1 + c_SRC[e]*NN*C1;

    float accv = 0.f;
    int i = 0;
    for (; i + 2 <= deg; i += 2) {
        int   r0 = sr[i],            r1 = sr[i+1];
        float w0 = w[i*H1 + h],      w1 = w[(i+1)*H1 + h];
        accv += w0 * hsrc[r0*C1 + c];
        accv += w1 * hsrc[r1*C1 + c];
    }
    if (i < deg)
        accv += w[i*H1 + h] * hsrc[sr[i]*C1 + c];
    out[c] = fmaxf(accv, 0.f);
}

// ---------------------------------------------------------------------------
// Semantic score + group softmax (tiny)
// ---------------------------------------------------------------------------
__global__ void k_score1(const float* __restrict__ q) {
    __shared__ float red[128];
    __shared__ float sc[NR];
    int t = threadIdx.x;
    for (int e = 0; e < NR; e++) {
        float p = q[t] * g_colsum1[e*C1 + t];
        red[t] = p; __syncthreads();
        for (int s = 64; s > 0; s >>= 1) {
            if (t < s) red[t] += red[t + s];
            __syncthreads();
        }
        if (t == 0) sc[e] = red[0] / (float)NN;
        __syncthreads();
    }
    if (t < NT) {
        int b = c_GRPOFF[t], e2 = c_GRPOFF[t+1];
        float m = -1e30f;
        for (int g = b; g < e2; g++) m = fmaxf(m, sc[c_GRP[g]]);
        float ssum = 0.f;
        for (int g = b; g < e2; g++) ssum += expf(sc[c_GRP[g]] - m);
        for (int g = b; g < e2; g++)
            g_sattn1[c_GRP[g]] = expf(sc[c_GRP[g]] - m) / ssum;
    }
}

__global__ void k_score2(const float* __restrict__ q) {
    __shared__ float red[128];
    __shared__ float sc[NR];
    int t = threadIdx.x;
    for (int e = 0; e < NR; e++) {
        float p = (t < C2) ? q[t] * g_colsum2[e*C2 + t] : 0.f;
        red[t] = p; __syncthreads();
        for (int s = 64; s > 0; s >>= 1) {
            if (t < s) red[t] += red[t + s];
            __syncthreads();
        }
        if (t == 0) sc[e] = red[0] / (float)NN;
        __syncthreads();
    }
    if (t < NT) {
        int b = c_GRPOFF[t], e2 = c_GRPOFF[t+1];
        float m = -1e30f;
        for (int g = b; g < e2; g++) m = fmaxf(m, sc[c_GRP[g]]);
        float ssum = 0.f;
        for (int g = b; g < e2; g++) ssum += expf(sc[c_GRP[g]] - m);
        for (int g = b; g < e2; g++)
            g_sattn2[c_GRP[g]] = expf(sc[c_GRP[g]] - m) / ssum;
    }
}

// ---------------------------------------------------------------------------
// Fuse relations per dst type (layer1) + elu -> x2
// ---------------------------------------------------------------------------
__global__ void k_combine1() {
    long idx = (long)blockIdx.x * blockDim.x + threadIdx.x;
    if (idx >= (long)NT*NN*C1) return;
    int t  = (int)(idx / (NN*C1));
    int nc = (int)(idx - (long)t*NN*C1);
    float v = 0.f;
    for (int g = c_GRPOFF[t]; g < c_GRPOFF[t+1]; g++) {
        int e = c_GRP[g];
        v += g_sattn1[e] * g_out1[(long)e*NN*C1 + nc];
    }
    g_x2[idx] = v > 0.f ? v : expf(v) - 1.f;
}

// ---------------------------------------------------------------------------
// Layer 2 logits (H=1): warp per (relation, node)
// ---------------------------------------------------------------------------
__global__ void k_logits2(const float* __restrict__ att_src,
                          const float* __restrict__ att_dst)
{
    int e = blockIdx.y;
    int n = blockIdx.x * 8 + (threadIdx.x >> 5);
    if (n >= NN) return;
    int l = threadIdx.x & 31;
    float ps = g_h2[c_SRC[e]*NN*C2 + n*C2 + l] * att_src[e*C2 + l];
    float pd = g_h2[c_DST[e]*NN*C2 + n*C2 + l] * att_dst[e*C2 + l];
#pragma unroll
    for (int o = 16; o > 0; o >>= 1) {
        ps += __shfl_xor_sync(0xffffffffu, ps, o);
        pd += __shfl_xor_sync(0xffffffffu, pd, o);
    }
    if (l == 0) { g_asrc2[e*NN + n] = ps; g_adst2[e*NN + n] = pd; }
}

// ---------------------------------------------------------------------------
// Segment softmax, layer 2: one warp per (relation, node), H=1
// ---------------------------------------------------------------------------
__global__ void k_soft2() {
    int e = blockIdx.y;
    int n = blockIdx.x * 8 + (threadIdx.x >> 5);
    if (n >= NN) return;
    int l = threadIdx.x & 31;

    int off = g_offsets[e*(NN+1) + n];
    int deg = g_offsets[e*(NN+1) + n + 1] - off;
    if (deg == 0) return;

    const int*   sr  = g_srcs + e*NE + off;
    const float* asr = g_asrc2 + e*NN;
    float ad = g_adst2[e*NN + n];

    float m = -1e30f, s = 0.f;
    for (int i = l; i < deg; i += 32) {
        float a = asr[sr[i]] + ad;
        a = a > 0.f ? a : 0.2f * a;
        if (a > m) { s = s * expf(m - a) + 1.f; m = a; }
        else        s += expf(a - m);
    }
#pragma unroll
    for (int o = 1; o <= 16; o <<= 1) {
        float mo = __shfl_xor_sync(0xffffffffu, m, o);
        float so = __shfl_xor_sync(0xffffffffu, s, o);
        float mn = fmaxf(m, mo);
        s = s * expf(m - mn) + so * expf(mo - mn);
        m = mn;
    }
    float inv = 1.f / (s + 1e-16f);
    float* w = g_w2 + e*NE + off;
    for (int i = l; i < deg; i += 32) {
        float a = asr[sr[i]] + ad;
        a = a > 0.f ? a : 0.2f * a;
        w[i] = expf(a - m) * inv;
    }
}

// ---------------------------------------------------------------------------
// Aggregation layer 2: warp per (node, relation)
// ---------------------------------------------------------------------------
__global__ void k_agg2() {
    int e = blockIdx.y;
    int n = blockIdx.x * 4 + (threadIdx.x >> 5);
    if (n >= NN) return;
    int c = threadIdx.x & 31;
    int off = g_offsets[e*(NN+1) + n];
    int deg = g_offsets[e*(NN+1) + n + 1] - off;
    float* out = g_out2 + (long)(e*NN + n) * C2;
    if (deg == 0) { out[c] = 0.f; return; }

    const int*   sr = g_srcs + e*NE + off;
    const float* w  = g_w2 + e*NE + off;
    const float* hsrc = g_h2 + c_SRC[e]*NN*C2;

    float accv = 0.f;
    int i = 0;
    for (; i + 2 <= deg; i += 2) {
        accv += w[i]   * hsrc[sr[i]*C2 + c];
        accv += w[i+1] * hsrc[sr[i+1]*C2 + c];
    }
    if (i < deg)
        accv += w[i] * hsrc[sr[i]*C2 + c];
    out[c] = fmaxf(accv, 0.f);
}

// ---------------------------------------------------------------------------
// Fuse relations layer 2 + final per-node channel softmax -> d_out
// ---------------------------------------------------------------------------
__global__ void k_combine2(float* __restrict__ out) {
    int g = blockIdx.x * 8 + (threadIdx.x >> 5);
    if (g >= NT*NN) return;
    int t = g / NN, n = g - t*NN;
    int c = threadIdx.x & 31;
    float v = 0.f;
    for (int gi = c_GRPOFF[t]; gi < c_GRPOFF[t+1]; gi++) {
        int e = c_GRP[gi];
        v += g_sattn2[e] * g_out2[(long)(e*NN + n)*C2 + c];
    }
    float m = v;
#pragma unroll
    for (int o = 16; o > 0; o >>= 1)
        m = fmaxf(m, __shfl_xor_sync(0xffffffffu, m, o));
    float ex = expf(v - m);
    float s = ex;
#pragma unroll
    for (int o = 16; o > 0; o >>= 1)
        s += __shfl_xor_sync(0xffffffffu, s, o);
    out[(long)g*C2 + c] = ex / s;
}

// ---------------------------------------------------------------------------
// Host launcher
// ---------------------------------------------------------------------------
extern "C" void kernel_launch(void* const* d_in, const int* in_sizes, int n_in,
                              void* d_out, int out_size)
{
    const float* x[4] = {(const float*)d_in[0], (const float*)d_in[1],
                         (const float*)d_in[2], (const float*)d_in[3]};
    const int*   edges    = (const int*)  d_in[4];
    const float* proj1_W  = (const float*)d_in[5];
    const float* proj1_b  = (const float*)d_in[6];
    const float* att1_src = (const float*)d_in[7];
    const float* att1_dst = (const float*)d_in[8];
    const float* k1_W     = (const float*)d_in[9];
    const float* k1_b     = (const float*)d_in[10];
    const float* q1       = (const float*)d_in[11];
    const float* proj2_W  = (const float*)d_in[12];
    const float* proj2_b  = (const float*)d_in[13];
    const float* att2_src = (const float*)d_in[14];
    const float* att2_dst = (const float*)d_in[15];
    const float* k2_W     = (const float*)d_in[16];
    const float* k2_b     = (const float*)d_in[17];
    const float* q2       = (const float*)d_in[18];
    float* out = (float*)d_out;

    float *h1p, *x2p, *h2p, *out1p, *out2p, *cs1p, *cs2p;
    __nv_bfloat16 *whi, *wlo;
    cudaGetSymbolAddress((void**)&h1p,   g_h1);
    cudaGetSymbolAddress((void**)&x2p,   g_x2);
    cudaGetSymbolAddress((void**)&h2p,   g_h2);
    cudaGetSymbolAddress((void**)&out1p, g_out1);
    cudaGetSymbolAddress((void**)&out2p, g_out2);
    cudaGetSymbolAddress((void**)&cs1p,  g_colsum1);
    cudaGetSymbolAddress((void**)&cs2p,  g_colsum2);
    cudaGetSymbolAddress((void**)&whi,   g_whi);
    cudaGetSymbolAddress((void**)&wlo,   g_wlo);

    const int MT = (NN + 127) / 128;   // 235 row tiles

    // zero + weight conversion + CSR build
    k_zero <<<(NR*NN + 255)/256, 256>>>();
    k_convW<<<dim3((IN1*C1 + 255)/256, 1, 4), 256>>>(proj1_W, whi+OFF_P1, wlo+OFF_P1, IN1, C1);
    k_convW<<<dim3((C1*C1  + 255)/256, 1, 1), 256>>>(k1_W,    whi+OFF_K1, wlo+OFF_K1, C1,  C1);
    k_convW<<<dim3((C1*C2  + 255)/256, 1, 4), 256>>>(proj2_W, whi+OFF_P2, wlo+OFF_P2, C1,  C2);
    k_convW<<<dim3((C2*C2  + 255)/256, 1, 1), 256>>>(k2_W,    whi+OFF_K2, wlo+OFF_K2, C2,  C2);
    k_count<<<(NR*NE + 255)/256, 256>>>(edges);
    k_scan <<<NR, 1024>>>();
    k_fill <<<(NR*NE + 255)/256, 256>>>(edges);

    // ---- layer 1 ----
    for (int t = 0; t < NT; t++)
        k_tmma<128, true, 0><<<MT, 256>>>(
            x[t], whi + OFF_P1 + (long)t*IN1*C1, wlo + OFF_P1 + (long)t*IN1*C1,
            proj1_b + t*C1, h1p + (long)t*NN*C1, NN, IN1,
            0, 0, 0, 0, nullptr, 0);

    k_logits1<<<dim3((NN + 7)/8, NR), 256>>>(att1_src, att1_dst);
    k_soft1  <<<dim3((NN + 7)/8, NR), 256>>>();
    k_agg1   <<<dim3(NN, NR), 128>>>();

    k_tmma<128, false, 1><<<dim3(MT, 1, NR), 256>>>(
        out1p, whi + OFF_K1, nullptr, k1_b, nullptr, NN, C1,
        (long)NN*C1, 0, 0, 0, cs1p, C1);
    k_score1<<<1, 128>>>(q1);
    k_combine1<<<((long)NT*NN*C1 + 255)/256, 256>>>();

    // ---- layer 2 ----
    k_tmma<32, true, 0><<<dim3(MT, 1, NT), 256>>>(
        x2p, whi + OFF_P2, wlo + OFF_P2, proj2_b, h2p, NN, C1,
        (long)NN*C1, (long)C1*C2, C2, (long)NN*C2, nullptr, 0);

    k_logits2<<<dim3((NN + 7)/8, NR), 256>>>(att2_src, att2_dst);
    k_soft2  <<<dim3((NN + 7)/8, NR), 256>>>();
    k_agg2   <<<dim3((NN + 3)/4, NR), 128>>>();

    k_tmma<32, false, 1><<<dim3(MT, 1, NR), 256>>>(
        out2p, whi + OFF_K2, nullptr, k2_b, nullptr, NN, C2,
        (long)NN*C2, 0, 0, 0, cs2p, C2);
    k_score2<<<1, 128>>>(q2);

    k_combine2<<<(NT*NN + 7)/8, 256>>>(out);
}

// round 6
// speedup vs baseline: 1.1597x; 1.1597x over previous
#include <cuda_runtime.h>
#include <math.h>

// ---------------------------------------------------------------------------
// Problem constants
// ---------------------------------------------------------------------------
constexpr int NN  = 30000;    // nodes per type
constexpr int NE  = 400000;   // edges per relation
constexpr int NR  = 10;       // relations
constexpr int NT  = 4;        // node types
constexpr int C1  = 128;      // layer1 channels
constexpr int H1  = 8;        // layer1 heads
constexpr int IN1 = 256;      // layer1 input dim
constexpr int C2  = 32;       // layer2 channels

__constant__ int c_SRC[NR]    = {0,1,2,3,0,1,2,1,3,1};
__constant__ int c_DST[NR]    = {0,1,2,3,1,0,1,2,1,3};
__constant__ int c_GRPOFF[5]  = {0,2,6,8,10};
__constant__ int c_GRP[NR]    = {0,5, 1,4,6,8, 2,7, 3,9};

// ---------------------------------------------------------------------------
// Scratch (static device arrays: allocation-free)
// ---------------------------------------------------------------------------
__device__ __align__(16) float g_h1   [NT*NN*C1];
__device__ __align__(16) float g_asrc1[NR*NN*H1];
__device__ __align__(16) float g_adst1[NR*NN*H1];
__device__ __align__(16) float g_out1 [NR*NN*C1];
__device__ __align__(16) float g_x2   [NT*NN*C1];
__device__ __align__(16) float g_h2   [NT*NN*C2];
__device__ __align__(16) float g_asrc2[NR*NN];
__device__ __align__(16) float g_adst2[NR*NN];
__device__ __align__(16) float g_out2 [NR*NN*C2];
__device__ float g_colsum1[NR*C1];
__device__ float g_colsum2[NR*C2];
__device__ float g_sattn1[NR];
__device__ float g_sattn2[NR];
__device__ int   g_counts [NR*NN];
__device__ int   g_offsets[NR*(NN+1)];
__device__ int   g_cursor [NR*NN];
__device__ int   g_srcs   [NR*NE];
__device__ __align__(16) float g_w1[(long)NR*NE*H1];
__device__ __align__(16) float g_w2[NR*NE];

// ---------------------------------------------------------------------------
// Packed f32x2 helpers (FFMA2 — only reachable via PTX, see SASS_QUICKREF)
// ---------------------------------------------------------------------------
__device__ __forceinline__ void ffma2(unsigned long long& c,
                                      unsigned long long a,
                                      unsigned long long b) {
    asm("fma.rn.f32x2 %0, %1, %2, %0;" : "+l"(c) : "l"(a), "l"(b));
}
__device__ __forceinline__ unsigned long long pk2(float x, float y) {
    unsigned long long r;
    asm("mov.b64 %0, {%1, %2};" : "=l"(r) : "f"(x), "f"(y));
    return r;
}
__device__ __forceinline__ float2 upk(unsigned long long v) {
    float2 r;
    asm("mov.b64 {%0, %1}, %2;" : "=f"(r.x), "=f"(r.y) : "l"(v));
    return r;
}

// ---------------------------------------------------------------------------
// Zeroing (counts + colsums)
// ---------------------------------------------------------------------------
__global__ void k_zero() {
    int i = blockIdx.x * blockDim.x + threadIdx.x;
    if (i < NR*NN) g_counts[i] = 0;
    if (i < NR*C1) g_colsum1[i] = 0.f;
    if (i < NR*C2) g_colsum2[i] = 0.f;
}

// ---------------------------------------------------------------------------
// CSR build by destination (shared by both layers)
// ---------------------------------------------------------------------------
__global__ void k_count(const int* __restrict__ edges) {
    int idx = blockIdx.x * blockDim.x + threadIdx.x;
    if (idx >= NR*NE) return;
    int e = idx / NE, i = idx - e*NE;
    int col = edges[e*2*NE + NE + i];
    atomicAdd(&g_counts[e*NN + col], 1);
}

__global__ void k_scan() {   // one block (1024 threads) per relation
    const int e = blockIdx.x;
    const int t = threadIdx.x;
    constexpr int CH = 30;
    int base = t * CH;
    int cnt[CH];
    int sum = 0;
#pragma unroll
    for (int i = 0; i < CH; i++) {
        int idx = base + i;
        int v = (idx < NN) ? g_counts[e*NN + idx] : 0;
        cnt[i] = v; sum += v;
    }
    __shared__ int s[1024];
    s[t] = sum; __syncthreads();
    for (int d = 1; d < 1024; d <<= 1) {
        int v = (t >= d) ? s[t-d] : 0;
        __syncthreads();
        s[t] += v;
        __syncthreads();
    }
    int run = s[t] - sum;
#pragma unroll
    for (int i = 0; i < CH; i++) {
        int idx = base + i;
        if (idx < NN) {
            g_offsets[e*(NN+1) + idx] = run;
            g_cursor [e*NN + idx]     = run;
            run += cnt[i];
        }
    }
    if (t == 1023) g_offsets[e*(NN+1) + NN] = s[1023];
}

__global__ void k_fill(const int* __restrict__ edges) {
    int idx = blockIdx.x * blockDim.x + threadIdx.x;
    if (idx >= NR*NE) return;
    int e = idx / NE, i = idx - e*NE;
    int row = edges[e*2*NE + i];
    int col = edges[e*2*NE + NE + i];
    int pos = atomicAdd(&g_cursor[e*NN + col], 1);
    g_srcs[e*NE + pos] = row;
}

// ---------------------------------------------------------------------------
// fp32 GEMM with packed FFMA2 mainloop.
// C[MxN] = A[MxK] @ B[KxN] (+bias).
// MODE 0: store C + bias.  MODE 1: colsum[col] += sum_rows tanh(C + bias).
// BM=BN=128, BK=16, 256 threads, 8x8 microtile (stored as 8 x 4 f32x2 pairs).
// ---------------------------------------------------------------------------
template <int MODE>
__global__ void __launch_bounds__(256)
k_gemm(const float* __restrict__ A, const float* __restrict__ B,
       const float* __restrict__ bias, float* __restrict__ C,
       int M, int Ncols, int K, long strideA, long strideC,
       float* __restrict__ colsum, int colsumStride)
{
    constexpr int BM = 128, BN = 128, BK = 16;
    __shared__ float As[BK][BM];
    __shared__ float Bs[BK][BN];

    const int z = blockIdx.z;
    A += (long)z * strideA;
    if (MODE == 0) C += (long)z * strideC;

    const int m0 = blockIdx.x * BM;
    const int n0 = blockIdx.y * BN;
    const int tid = threadIdx.x;
    const int tx = tid & 15, ty = tid >> 4;

    unsigned long long acc2[8][4];
#pragma unroll
    for (int i = 0; i < 8; i++)
#pragma unroll
        for (int j = 0; j < 4; j++) acc2[i][j] = 0ull;

    for (int k0 = 0; k0 < K; k0 += BK) {
        // load A tile (transposed into As[k][m])
#pragma unroll
        for (int it = 0; it < 2; it++) {
            int lin = tid + it * 256;
            int m = lin >> 2, kq = lin & 3;
            float4 v = {0.f, 0.f, 0.f, 0.f};
            if (m0 + m < M)
                v = *reinterpret_cast<const float4*>(A + (long)(m0+m)*K + k0 + kq*4);
            As[kq*4+0][m] = v.x; As[kq*4+1][m] = v.y;
            As[kq*4+2][m] = v.z; As[kq*4+3][m] = v.w;
        }
        // load B tile
#pragma unroll
        for (int it = 0; it < 2; it++) {
            int lin = tid + it * 256;
            int k = lin >> 5, nq = lin & 31;
            float4 v = {0.f, 0.f, 0.f, 0.f};
            if (n0 + nq*4 + 3 < Ncols)
                v = *reinterpret_cast<const float4*>(B + (long)(k0+k)*Ncols + n0 + nq*4);
            *reinterpret_cast<float4*>(&Bs[k][nq*4]) = v;
        }
        __syncthreads();
#pragma unroll
        for (int k = 0; k < BK; k++) {
            const float2* ap = reinterpret_cast<const float2*>(&As[k][ty*8]);
            const float2* bp = reinterpret_cast<const float2*>(&Bs[k][tx*8]);
            float2 af0 = ap[0], af1 = ap[1], af2 = ap[2], af3 = ap[3];
            float2 bf0 = bp[0], bf1 = bp[1], bf2 = bp[2], bf3 = bp[3];
            unsigned long long b2[4];
            b2[0] = pk2(bf0.x, bf0.y);
            b2[1] = pk2(bf1.x, bf1.y);
            b2[2] = pk2(bf2.x, bf2.y);
            b2[3] = pk2(bf3.x, bf3.y);
            float a[8] = {af0.x, af0.y, af1.x, af1.y, af2.x, af2.y, af3.x, af3.y};
#pragma unroll
            for (int i = 0; i < 8; i++) {
                unsigned long long a2 = pk2(a[i], a[i]);
#pragma unroll
                for (int j = 0; j < 4; j++) ffma2(acc2[i][j], a2, b2[j]);
            }
        }
        __syncthreads();
    }

    if (MODE == 0) {
#pragma unroll
        for (int i = 0; i < 8; i++) {
            int r = m0 + ty*8 + i;
            if (r >= M) continue;
#pragma unroll
            for (int j = 0; j < 4; j++) {
                int c = n0 + tx*8 + j*2;
                if (c + 1 < Ncols) {
                    float2 v = upk(acc2[i][j]);
                    v.x += bias[c]; v.y += bias[c+1];
                    *reinterpret_cast<float2*>(&C[(long)r*Ncols + c]) = v;
                } else if (c < Ncols) {
                    float2 v = upk(acc2[i][j]);
                    C[(long)r*Ncols + c] = v.x + bias[c];
                }
            }
        }
    } else {
        __shared__ float cs[BN];
        if (tid < BN) cs[tid] = 0.f;
        __syncthreads();
#pragma unroll
        for (int j = 0; j < 4; j++) {
            int c = n0 + tx*8 + j*2;
            if (c < Ncols) {
                float b0 = bias[c];
                float b1 = (c + 1 < Ncols) ? bias[c+1] : 0.f;
                float s0 = 0.f, s1 = 0.f;
#pragma unroll
                for (int i = 0; i < 8; i++) {
                    int r = m0 + ty*8 + i;
                    if (r < M) {
                        float2 v = upk(acc2[i][j]);
                        s0 += tanhf(v.x + b0);
                        s1 += tanhf(v.y + b1);
                    }
                }
                atomicAdd(&cs[tx*8 + j*2], s0);
                if (c + 1 < Ncols) atomicAdd(&cs[tx*8 + j*2 + 1], s1);
            }
        }
        __syncthreads();
        if (tid < BN && n0 + tid < Ncols)
            atomicAdd(&colsum[z*colsumStride + n0 + tid], cs[tid]);
    }
}

// ---------------------------------------------------------------------------
// Attention logits, layer 1: warp per (relation, node)
// ---------------------------------------------------------------------------
__global__ void k_logits1(const float* __restrict__ att_src,
                          const float* __restrict__ att_dst)
{
    int e = blockIdx.y;
    int n = blockIdx.x * 8 + (threadIdx.x >> 5);
    if (n >= NN) return;
    int l = threadIdx.x & 31;

    const float4* hs = reinterpret_cast<const float4*>(g_h1 + c_SRC[e]*NN*C1 + n*C1);
    const float4* hd = reinterpret_cast<const float4*>(g_h1 + c_DST[e]*NN*C1 + n*C1);
    const float4* as = reinterpret_cast<const float4*>(att_src + e*C1);
    const float4* ad = reinterpret_cast<const float4*>(att_dst + e*C1);

    float4 a = hs[l], b = as[l];
    float ps = a.x*b.x + a.y*b.y + a.z*b.z + a.w*b.w;
    float4 c = hd[l], d = ad[l];
    float pd = c.x*d.x + c.y*d.y + c.z*d.z + c.w*d.w;
    ps += __shfl_xor_sync(0xffffffffu, ps, 1);
    ps += __shfl_xor_sync(0xffffffffu, ps, 2);
    pd += __shfl_xor_sync(0xffffffffu, pd, 1);
    pd += __shfl_xor_sync(0xffffffffu, pd, 2);
    if ((l & 3) == 0) {
        g_asrc1[(e*NN + n)*H1 + (l >> 2)] = ps;
        g_adst1[(e*NN + n)*H1 + (l >> 2)] = pd;
    }
}

// ---------------------------------------------------------------------------
// Segment softmax, layer 1: one warp per (relation, node)
// ---------------------------------------------------------------------------
__global__ void k_soft1() {
    int e = blockIdx.y;
    int n = blockIdx.x * 8 + (threadIdx.x >> 5);
    if (n >= NN) return;
    int l  = threadIdx.x & 31;
    int h  = l >> 2;
    int il = l & 3;

    int off = g_offsets[e*(NN+1) + n];
    int deg = g_offsets[e*(NN+1) + n + 1] - off;
    if (deg == 0) return;

    const int*   sr  = g_srcs + e*NE + off;
    const float* asr = g_asrc1 + e*NN*H1;
    float ad = g_adst1[(e*NN + n)*H1 + h];

    float m = -1e30f, s = 0.f;
    for (int i = il; i < deg; i += 4) {
        float a = asr[sr[i]*H1 + h] + ad;
        a = a > 0.f ? a : 0.2f * a;
        if (a > m) { s = s * expf(m - a) + 1.f; m = a; }
        else        s += expf(a - m);
    }
#pragma unroll
    for (int o = 1; o <= 2; o <<= 1) {
        float mo = __shfl_xor_sync(0xffffffffu, m, o);
        float so = __shfl_xor_sync(0xffffffffu, s, o);
        float mn = fmaxf(m, mo);
        s = s * expf(m - mn) + so * expf(mo - mn);
        m = mn;
    }
    float inv = 1.f / (s + 1e-16f);
    float* w = g_w1 + (long)(e*NE + off) * H1;
    for (int i = il; i < deg; i += 4) {
        float a = asr[sr[i]*H1 + h] + ad;
        a = a > 0.f ? a : 0.2f * a;
        w[i*H1 + h] = expf(a - m) * inv;
    }
}

// ---------------------------------------------------------------------------
// Aggregation layer 1: pure weighted gather
// ---------------------------------------------------------------------------
__global__ void k_agg1() {
    int e = blockIdx.y, n = blockIdx.x;
    int c = threadIdx.x;
    int h = c >> 4;
    int off = g_offsets[e*(NN+1) + n];
    int deg = g_offsets[e*(NN+1) + n + 1] - off;
    float* out = g_out1 + (long)(e*NN + n) * C1;
    if (deg == 0) { out[c] = 0.f; return; }

    const int*   sr = g_srcs + e*NE + off;
    const float* w  = g_w1 + (long)(e*NE + off) * H1;
    const float* hsrc = g_h1 + c_SRC[e]*NN*C1;

    float accv = 0.f;
    int i = 0;
    for (; i + 2 <= deg; i += 2) {
        int   r0 = sr[i],            r1 = sr[i+1];
        float w0 = w[i*H1 + h],      w1 = w[(i+1)*H1 + h];
        accv += w0 * hsrc[r0*C1 + c];
        accv += w1 * hsrc[r1*C1 + c];
    }
    if (i < deg)
        accv += w[i*H1 + h] * hsrc[sr[i]*C1 + c];
    out[c] = fmaxf(accv, 0.f);
}

// ---------------------------------------------------------------------------
// Semantic score + group softmax (tiny)
// ---------------------------------------------------------------------------
__global__ void k_score1(const float* __restrict__ q) {
    __shared__ float red[128];
    __shared__ float sc[NR];
    int t = threadIdx.x;
    for (int e = 0; e < NR; e++) {
        float p = q[t] * g_colsum1[e*C1 + t];
        red[t] = p; __syncthreads();
        for (int s = 64; s > 0; s >>= 1) {
            if (t < s) red[t] += red[t + s];
            __syncthreads();
        }
        if (t == 0) sc[e] = red[0] / (float)NN;
        __syncthreads();
    }
    if (t < NT) {
        int b = c_GRPOFF[t], e2 = c_GRPOFF[t+1];
        float m = -1e30f;
        for (int g = b; g < e2; g++) m = fmaxf(m, sc[c_GRP[g]]);
        float ssum = 0.f;
        for (int g = b; g < e2; g++) ssum += expf(sc[c_GRP[g]] - m);
        for (int g = b; g < e2; g++)
            g_sattn1[c_GRP[g]] = expf(sc[c_GRP[g]] - m) / ssum;
    }
}

__global__ void k_score2(const float* __restrict__ q) {
    __shared__ float red[128];
    __shared__ float sc[NR];
    int t = threadIdx.x;
    for (int e = 0; e < NR; e++) {
        float p = (t < C2) ? q[t] * g_colsum2[e*C2 + t] : 0.f;
        red[t] = p; __syncthreads();
        for (int s = 64; s > 0; s >>= 1) {
            if (t < s) red[t] += red[t + s];
            __syncthreads();
        }
        if (t == 0) sc[e] = red[0] / (float)NN;
        __syncthreads();
    }
    if (t < NT) {
        int b = c_GRPOFF[t], e2 = c_GRPOFF[t+1];
        float m = -1e30f;
        for (int g = b; g < e2; g++) m = fmaxf(m, sc[c_GRP[g]]);
        float ssum = 0.f;
        for (int g = b; g < e2; g++) ssum += expf(sc[c_GRP[g]] - m);
        for (int g = b; g < e2; g++)
            g_sattn2[c_GRP[g]] = expf(sc[c_GRP[g]] - m) / ssum;
    }
}

// ---------------------------------------------------------------------------
// Fuse relations per dst type (layer1) + elu -> x2
// ---------------------------------------------------------------------------
__global__ void k_combine1() {
    long idx = (long)blockIdx.x * blockDim.x + threadIdx.x;
    if (idx >= (long)NT*NN*C1) return;
    int t  = (int)(idx / (NN*C1));
    int nc = (int)(idx - (long)t*NN*C1);
    float v = 0.f;
    for (int g = c_GRPOFF[t]; g < c_GRPOFF[t+1]; g++) {
        int e = c_GRP[g];
        v += g_sattn1[e] * g_out1[(long)e*NN*C1 + nc];
    }
    g_x2[idx] = v > 0.f ? v : expf(v) - 1.f;
}

// ---------------------------------------------------------------------------
// Layer 2 logits (H=1): warp per (relation, node)
// ---------------------------------------------------------------------------
__global__ void k_logits2(const float* __restrict__ att_src,
                          const float* __restrict__ att_dst)
{
    int e = blockIdx.y;
    int n = blockIdx.x * 8 + (threadIdx.x >> 5);
    if (n >= NN) return;
    int l = threadIdx.x & 31;
    float ps = g_h2[c_SRC[e]*NN*C2 + n*C2 + l] * att_src[e*C2 + l];
    float pd = g_h2[c_DST[e]*NN*C2 + n*C2 + l] * att_dst[e*C2 + l];
#pragma unroll
    for (int o = 16; o > 0; o >>= 1) {
        ps += __shfl_xor_sync(0xffffffffu, ps, o);
        pd += __shfl_xor_sync(0xffffffffu, pd, o);
    }
    if (l == 0) { g_asrc2[e*NN + n] = ps; g_adst2[e*NN + n] = pd; }
}

// ---------------------------------------------------------------------------
// Segment softmax, layer 2: one warp per (relation, node), H=1
// ---------------------------------------------------------------------------
__global__ void k_soft2() {
    int e = blockIdx.y;
    int n = blockIdx.x * 8 + (threadIdx.x >> 5);
    if (n >= NN) return;
    int l = threadIdx.x & 31;

    int off = g_offsets[e*(NN+1) + n];
    int deg = g_offsets[e*(NN+1) + n + 1] - off;
    if (deg == 0) return;

    const int*   sr  = g_srcs + e*NE + off;
    const float* asr = g_asrc2 + e*NN;
    float ad = g_adst2[e*NN + n];

    float m = -1e30f, s = 0.f;
    for (int i = l; i < deg; i += 32) {
        float a = asr[sr[i]] + ad;
        a = a > 0.f ? a : 0.2f * a;
        if (a > m) { s = s * expf(m - a) + 1.f; m = a; }
        else        s += expf(a - m);
    }
#pragma unroll
    for (int o = 1; o <= 16; o <<= 1) {
        float mo = __shfl_xor_sync(0xffffffffu, m, o);
        float so = __shfl_xor_sync(0xffffffffu, s, o);
        float mn = fmaxf(m, mo);
        s = s * expf(m - mn) + so * expf(mo - mn);
        m = mn;
    }
    float inv = 1.f / (s + 1e-16f);
    float* w = g_w2 + e*NE + off;
    for (int i = l; i < deg; i += 32) {
        float a = asr[sr[i]] + ad;
        a = a > 0.f ? a : 0.2f * a;
        w[i] = expf(a - m) * inv;
    }
}

// ---------------------------------------------------------------------------
// Aggregation layer 2: warp per (node, relation)
// ---------------------------------------------------------------------------
__global__ void k_agg2() {
    int e = blockIdx.y;
    int n = blockIdx.x * 4 + (threadIdx.x >> 5);
    if (n >= NN) return;
    int c = threadIdx.x & 31;
    int off = g_offsets[e*(NN+1) + n];
    int deg = g_offsets[e*(NN+1) + n + 1] - off;
    float* out = g_out2 + (long)(e*NN + n) * C2;
    if (deg == 0) { out[c] = 0.f; return; }

    const int*   sr = g_srcs + e*NE + off;
    const float* w  = g_w2 + e*NE + off;
    const float* hsrc = g_h2 + c_SRC[e]*NN*C2;

    float accv = 0.f;
    int i = 0;
    for (; i + 2 <= deg; i += 2) {
        accv += w[i]   * hsrc[sr[i]*C2 + c];
        accv += w[i+1] * hsrc[sr[i+1]*C2 + c];
    }
    if (i < deg)
        accv += w[i] * hsrc[sr[i]*C2 + c];
    out[c] = fmaxf(accv, 0.f);
}

// ---------------------------------------------------------------------------
// Fuse relations layer 2 + final per-node channel softmax -> d_out
// ---------------------------------------------------------------------------
__global__ void k_combine2(float* __restrict__ out) {
    int g = blockIdx.x * 8 + (threadIdx.x >> 5);
    if (g >= NT*NN) return;
    int t = g / NN, n = g - t*NN;
    int c = threadIdx.x & 31;
    float v = 0.f;
    for (int gi = c_GRPOFF[t]; gi < c_GRPOFF[t+1]; gi++) {
        int e = c_GRP[gi];
        v += g_sattn2[e] * g_out2[(long)(e*NN + n)*C2 + c];
    }
    float m = v;
#pragma unroll
    for (int o = 16; o > 0; o >>= 1)
        m = fmaxf(m, __shfl_xor_sync(0xffffffffu, m, o));
    float ex = expf(v - m);
    float s = ex;
#pragma unroll
    for (int o = 16; o > 0; o >>= 1)
        s += __shfl_xor_sync(0xffffffffu, s, o);
    out[(long)g*C2 + c] = ex / s;
}

// ---------------------------------------------------------------------------
// Host launcher
// ---------------------------------------------------------------------------
extern "C" void kernel_launch(void* const* d_in, const int* in_sizes, int n_in,
                              void* d_out, int out_size)
{
    const float* x[4] = {(const float*)d_in[0], (const float*)d_in[1],
                         (const float*)d_in[2], (const float*)d_in[3]};
    const int*   edges    = (const int*)  d_in[4];
    const float* proj1_W  = (const float*)d_in[5];
    const float* proj1_b  = (const float*)d_in[6];
    const float* att1_src = (const float*)d_in[7];
    const float* att1_dst = (const float*)d_in[8];
    const float* k1_W     = (const float*)d_in[9];
    const float* k1_b     = (const float*)d_in[10];
    const float* q1       = (const float*)d_in[11];
    const float* proj2_W  = (const float*)d_in[12];
    const float* proj2_b  = (const float*)d_in[13];
    const float* att2_src = (const float*)d_in[14];
    const float* att2_dst = (const float*)d_in[15];
    const float* k2_W     = (const float*)d_in[16];
    const float* k2_b     = (const float*)d_in[17];
    const float* q2       = (const float*)d_in[18];
    float* out = (float*)d_out;

    float *h1p, *x2p, *h2p, *out1p, *out2p, *cs1p, *cs2p;
    cudaGetSymbolAddress((void**)&h1p,   g_h1);
    cudaGetSymbolAddress((void**)&x2p,   g_x2);
    cudaGetSymbolAddress((void**)&h2p,   g_h2);
    cudaGetSymbolAddress((void**)&out1p, g_out1);
    cudaGetSymbolAddress((void**)&out2p, g_out2);
    cudaGetSymbolAddress((void**)&cs1p,  g_colsum1);
    cudaGetSymbolAddress((void**)&cs2p,  g_colsum2);

    const int MT = (NN + 127) / 128;   // 235 row tiles

    // zero counts/colsums, build CSR (shared by both layers)
    k_zero <<<(NR*NN + 255)/256, 256>>>();
    k_count<<<(NR*NE + 255)/256, 256>>>(edges);
    k_scan <<<NR, 1024>>>();
    k_fill <<<(NR*NE + 255)/256, 256>>>(edges);

    // ---- layer 1 ----
    for (int t = 0; t < NT; t++)
        k_gemm<0><<<dim3(MT, 1, 1), 256>>>(
            x[t], proj1_W + (long)t*IN1*C1, proj1_b + t*C1,
            h1p + (long)t*NN*C1, NN, C1, IN1, 0, 0, nullptr, 0);

    k_logits1<<<dim3((NN + 7)/8, NR), 256>>>(att1_src, att1_dst);
    k_soft1  <<<dim3((NN + 7)/8, NR), 256>>>();
    k_agg1   <<<dim3(NN, NR), 128>>>();

    k_gemm<1><<<dim3(MT, 1, NR), 256>>>(
        out1p, k1_W, k1_b, nullptr, NN, C1, C1,
        (long)NN*C1, 0, cs1p, C1);
    k_score1<<<1, 128>>>(q1);
    k_combine1<<<((long)NT*NN*C1 + 255)/256, 256>>>();

    // ---- layer 2 ----
    for (int t = 0; t < NT; t++)
        k_gemm<0><<<dim3(MT, 1, 1), 256>>>(
            x2p + (long)t*NN*C1, proj2_W + (long)t*C1*C2, proj2_b + t*C2,
            h2p + (long)t*NN*C2, NN, C2, C1, 0, 0, nullptr, 0);

    k_logits2<<<dim3((NN + 7)/8, NR), 256>>>(att2_src, att2_dst);
    k_soft2  <<<dim3((NN + 7)/8, NR), 256>>>();
    k_agg2   <<<dim3((NN + 3)/4, NR), 128>>>();

    k_gemm<1><<<dim3(MT, 1, NR), 256>>>(
        out2p, k2_W, k2_b, nullptr, NN, C2, C2,
        (long)NN*C2, 0, cs2p, C2);
    k_score2<<<1, 128>>>(q2);

    k_combine2<<<(NT*NN + 7)/8, 256>>>(out);
}

// round 7
// speedup vs baseline: 1.3007x; 1.1216x over previous
#include <cuda_runtime.h>
#include <math.h>

// ---------------------------------------------------------------------------
// Problem constants
// ---------------------------------------------------------------------------
constexpr int NN  = 30000;    // nodes per type
constexpr int NE  = 400000;   // edges per relation
constexpr int NR  = 10;       // relations
constexpr int NT  = 4;        // node types
constexpr int C1  = 128;      // layer1 channels
constexpr int H1  = 8;        // layer1 heads
constexpr int IN1 = 256;      // layer1 input dim
constexpr int C2  = 32;       // layer2 channels

__constant__ int c_SRC[NR]    = {0,1,2,3,0,1,2,1,3,1};
__constant__ int c_DST[NR]    = {0,1,2,3,1,0,1,2,1,3};
__constant__ int c_GRPOFF[5]  = {0,2,6,8,10};
__constant__ int c_GRP[NR]    = {0,5, 1,4,6,8, 2,7, 3,9};

// ---------------------------------------------------------------------------
// Scratch (static device arrays: allocation-free)
// ---------------------------------------------------------------------------
__device__ __align__(16) float g_h1   [NT*NN*C1];
__device__ __align__(16) float g_asrc1[NR*NN*H1];
__device__ __align__(16) float g_adst1[NR*NN*H1];
__device__ __align__(16) float g_out1 [NR*NN*C1];
__device__ __align__(16) float g_x2   [NT*NN*C1];
__device__ __align__(16) float g_h2   [NT*NN*C2];
__device__ __align__(16) float g_asrc2[NR*NN];
__device__ __align__(16) float g_adst2[NR*NN];
__device__ __align__(16) float g_out2 [NR*NN*C2];
__device__ float g_colsum1[NR*C1];
__device__ float g_colsum2[NR*C2];
__device__ float g_sattn1[NR];
__device__ float g_sattn2[NR];
__device__ int   g_counts [NR*NN];
__device__ int   g_offsets[NR*(NN+1)];
__device__ int   g_cursor [NR*NN];
__device__ int   g_srcs   [NR*NE];
__device__ __align__(16) float g_w1[(long)NR*NE*H1];
__device__ __align__(16) float g_w2[NR*NE];

// ---------------------------------------------------------------------------
// Packed f32x2 helpers (FFMA2)
// ---------------------------------------------------------------------------
__device__ __forceinline__ void ffma2(unsigned long long& c,
                                      unsigned long long a,
                                      unsigned long long b) {
    asm("fma.rn.f32x2 %0, %1, %2, %0;" : "+l"(c) : "l"(a), "l"(b));
}
__device__ __forceinline__ unsigned long long pk2(float x, float y) {
    unsigned long long r;
    asm("mov.b64 %0, {%1, %2};" : "=l"(r) : "f"(x), "f"(y));
    return r;
}
__device__ __forceinline__ float2 upk(unsigned long long v) {
    float2 r;
    asm("mov.b64 {%0, %1}, %2;" : "=f"(r.x), "=f"(r.y) : "l"(v));
    return r;
}

// ---------------------------------------------------------------------------
// Zeroing
// ---------------------------------------------------------------------------
__global__ void k_zero() {
    int i = blockIdx.x * blockDim.x + threadIdx.x;
    if (i < NR*NN) g_counts[i] = 0;
    if (i < NR*C1) g_colsum1[i] = 0.f;
    if (i < NR*C2) g_colsum2[i] = 0.f;
}

// ---------------------------------------------------------------------------
// CSR build by destination
// ---------------------------------------------------------------------------
__global__ void k_count(const int* __restrict__ edges) {
    int idx = blockIdx.x * blockDim.x + threadIdx.x;
    if (idx >= NR*NE) return;
    int e = idx / NE, i = idx - e*NE;
    int col = edges[e*2*NE + NE + i];
    atomicAdd(&g_counts[e*NN + col], 1);
}

__global__ void k_scan() {   // one block (1024 threads) per relation
    const int e = blockIdx.x;
    const int t = threadIdx.x;
    constexpr int CH = 30;
    int base = t * CH;
    int cnt[CH];
    int sum = 0;
#pragma unroll
    for (int i = 0; i < CH; i++) {
        int idx = base + i;
        int v = (idx < NN) ? g_counts[e*NN + idx] : 0;
        cnt[i] = v; sum += v;
    }
    __shared__ int s[1024];
    s[t] = sum; __syncthreads();
    for (int d = 1; d < 1024; d <<= 1) {
        int v = (t >= d) ? s[t-d] : 0;
        __syncthreads();
        s[t] += v;
        __syncthreads();
    }
    int run = s[t] - sum;
#pragma unroll
    for (int i = 0; i < CH; i++) {
        int idx = base + i;
        if (idx < NN) {
            g_offsets[e*(NN+1) + idx] = run;
            g_cursor [e*NN + idx]     = run;
            run += cnt[i];
        }
    }
    if (t == 1023) g_offsets[e*(NN+1) + NN] = s[1023];
}

__global__ void k_fill(const int* __restrict__ edges) {
    int idx = blockIdx.x * blockDim.x + threadIdx.x;
    if (idx >= NR*NE) return;
    int e = idx / NE, i = idx - e*NE;
    int row = edges[e*2*NE + i];
    int col = edges[e*2*NE + NE + i];
    int pos = atomicAdd(&g_cursor[e*NN + col], 1);
    g_srcs[e*NE + pos] = row;
}

// ---------------------------------------------------------------------------
// fp32 GEMM (FFMA2 mainloop). Batched over z: A chosen from A0..A3 or strided.
// MODE 0: C = acc + bias.  MODE 1: colsum[col] += sum_rows tanh(acc + bias).
// ---------------------------------------------------------------------------
template <int MODE>
__global__ void __launch_bounds__(256)
k_gemm(const float* __restrict__ A0, const float* __restrict__ A1,
       const float* __restrict__ A2, const float* __restrict__ A3,
       const float* __restrict__ B,
       const float* __restrict__ bias, float* __restrict__ C,
       int M, int Ncols, int K, long strideA, long strideB, long strideBias,
       long strideC, float* __restrict__ colsum, int colsumStride)
{
    constexpr int BM = 128, BN = 128, BK = 16;
    __shared__ float As[BK][BM];
    __shared__ float Bs[BK][BN];

    const int z = blockIdx.z;
    const float* A = strideA ? (A0 + (long)z * strideA)
                             : (z == 0 ? A0 : z == 1 ? A1 : z == 2 ? A2 : A3);
    B    += (long)z * strideB;
    bias += (long)z * strideBias;
    if (MODE == 0) C += (long)z * strideC;

    const int m0 = blockIdx.x * BM;
    const int n0 = blockIdx.y * BN;
    const int tid = threadIdx.x;
    const int tx = tid & 15, ty = tid >> 4;

    unsigned long long acc2[8][4];
#pragma unroll
    for (int i = 0; i < 8; i++)
#pragma unroll
        for (int j = 0; j < 4; j++) acc2[i][j] = 0ull;

    for (int k0 = 0; k0 < K; k0 += BK) {
#pragma unroll
        for (int it = 0; it < 2; it++) {
            int lin = tid + it * 256;
            int m = lin >> 2, kq = lin & 3;
            float4 v = {0.f, 0.f, 0.f, 0.f};
            if (m0 + m < M)
                v = *reinterpret_cast<const float4*>(A + (long)(m0+m)*K + k0 + kq*4);
            As[kq*4+0][m] = v.x; As[kq*4+1][m] = v.y;
            As[kq*4+2][m] = v.z; As[kq*4+3][m] = v.w;
        }
#pragma unroll
        for (int it = 0; it < 2; it++) {
            int lin = tid + it * 256;
            int k = lin >> 5, nq = lin & 31;
            float4 v = {0.f, 0.f, 0.f, 0.f};
            if (n0 + nq*4 + 3 < Ncols)
                v = *reinterpret_cast<const float4*>(B + (long)(k0+k)*Ncols + n0 + nq*4);
            *reinterpret_cast<float4*>(&Bs[k][nq*4]) = v;
        }
        __syncthreads();
#pragma unroll
        for (int k = 0; k < BK; k++) {
            const float2* ap = reinterpret_cast<const float2*>(&As[k][ty*8]);
            const float2* bp = reinterpret_cast<const float2*>(&Bs[k][tx*8]);
            float2 af0 = ap[0], af1 = ap[1], af2 = ap[2], af3 = ap[3];
            float2 bf0 = bp[0], bf1 = bp[1], bf2 = bp[2], bf3 = bp[3];
            unsigned long long b2[4];
            b2[0] = pk2(bf0.x, bf0.y);
            b2[1] = pk2(bf1.x, bf1.y);
            b2[2] = pk2(bf2.x, bf2.y);
            b2[3] = pk2(bf3.x, bf3.y);
            float a[8] = {af0.x, af0.y, af1.x, af1.y, af2.x, af2.y, af3.x, af3.y};
#pragma unroll
            for (int i = 0; i < 8; i++) {
                unsigned long long a2 = pk2(a[i], a[i]);
#pragma unroll
                for (int j = 0; j < 4; j++) ffma2(acc2[i][j], a2, b2[j]);
            }
        }
        __syncthreads();
    }

    if (MODE == 0) {
#pragma unroll
        for (int i = 0; i < 8; i++) {
            int r = m0 + ty*8 + i;
            if (r >= M) continue;
#pragma unroll
            for (int j = 0; j < 4; j++) {
                int c = n0 + tx*8 + j*2;
                if (c + 1 < Ncols) {
                    float2 v = upk(acc2[i][j]);
                    v.x += bias[c]; v.y += bias[c+1];
                    *reinterpret_cast<float2*>(&C[(long)r*Ncols + c]) = v;
                } else if (c < Ncols) {
                    float2 v = upk(acc2[i][j]);
                    C[(long)r*Ncols + c] = v.x + bias[c];
                }
            }
        }
    } else {
        __shared__ float cs[BN];
        if (tid < BN) cs[tid] = 0.f;
        __syncthreads();
#pragma unroll
        for (int j = 0; j < 4; j++) {
            int c = n0 + tx*8 + j*2;
            if (c < Ncols) {
                float b0 = bias[c];
                float b1 = (c + 1 < Ncols) ? bias[c+1] : 0.f;
                float s0 = 0.f, s1 = 0.f;
#pragma unroll
                for (int i = 0; i < 8; i++) {
                    int r = m0 + ty*8 + i;
                    if (r < M) {
                        float2 v = upk(acc2[i][j]);
                        s0 += tanhf(v.x + b0);
                        s1 += tanhf(v.y + b1);
                    }
                }
                atomicAdd(&cs[tx*8 + j*2], s0);
                if (c + 1 < Ncols) atomicAdd(&cs[tx*8 + j*2 + 1], s1);
            }
        }
        __syncthreads();
        if (tid < BN && n0 + tid < Ncols)
            atomicAdd(&colsum[z*colsumStride + n0 + tid], cs[tid]);
    }
}

// ---------------------------------------------------------------------------
// Attention logits, layer 1: warp per (relation, node)
// ---------------------------------------------------------------------------
__global__ void k_logits1(const float* __restrict__ att_src,
                          const float* __restrict__ att_dst)
{
    int e = blockIdx.y;
    int n = blockIdx.x * 8 + (threadIdx.x >> 5);
    if (n >= NN) return;
    int l = threadIdx.x & 31;

    const float4* hs = reinterpret_cast<const float4*>(g_h1 + c_SRC[e]*NN*C1 + n*C1);
    const float4* hd = reinterpret_cast<const float4*>(g_h1 + c_DST[e]*NN*C1 + n*C1);
    const float4* as = reinterpret_cast<const float4*>(att_src + e*C1);
    const float4* ad = reinterpret_cast<const float4*>(att_dst + e*C1);

    float4 a = hs[l], b = as[l];
    float ps = a.x*b.x + a.y*b.y + a.z*b.z + a.w*b.w;
    float4 c = hd[l], d = ad[l];
    float pd = c.x*d.x + c.y*d.y + c.z*d.z + c.w*d.w;
    ps += __shfl_xor_sync(0xffffffffu, ps, 1);
    ps += __shfl_xor_sync(0xffffffffu, ps, 2);
    pd += __shfl_xor_sync(0xffffffffu, pd, 1);
    pd += __shfl_xor_sync(0xffffffffu, pd, 2);
    if ((l & 3) == 0) {
        g_asrc1[(e*NN + n)*H1 + (l >> 2)] = ps;
        g_adst1[(e*NN + n)*H1 + (l >> 2)] = pd;
    }
}

// ---------------------------------------------------------------------------
// Segment softmax, layer 1: warp per (relation, node), two-pass via w buffer.
// Pass 1: gather logits, leaky-relu, write unnormalized to w, track (m, s).
// Pass 2: normalize w in place (sequential traffic only).
// ---------------------------------------------------------------------------
__global__ void k_soft1() {
    int e = blockIdx.y;
    int n = blockIdx.x * 8 + (threadIdx.x >> 5);
    if (n >= NN) return;
    int l  = threadIdx.x & 31;
    int h  = l >> 2;
    int il = l & 3;

    int off = g_offsets[e*(NN+1) + n];
    int deg = g_offsets[e*(NN+1) + n + 1] - off;
    if (deg == 0) return;

    const int*   sr  = g_srcs + e*NE + off;
    const float* asr = g_asrc1 + e*NN*H1;
    float ad = g_adst1[(e*NN + n)*H1 + h];
    float* w = g_w1 + (long)(e*NE + off) * H1;

    float m = -1e30f, s = 0.f;
    for (int i = il; i < deg; i += 4) {
        float a = asr[sr[i]*H1 + h] + ad;
        a = a > 0.f ? a : 0.2f * a;
        w[i*H1 + h] = a;
        if (a > m) { s = s * expf(m - a) + 1.f; m = a; }
        else        s += expf(a - m);
    }
#pragma unroll
    for (int o = 1; o <= 2; o <<= 1) {
        float mo = __shfl_xor_sync(0xffffffffu, m, o);
        float so = __shfl_xor_sync(0xffffffffu, s, o);
        float mn = fmaxf(m, mo);
        s = s * expf(m - mn) + so * expf(mo - mn);
        m = mn;
    }
    float inv = 1.f / (s + 1e-16f);
    for (int i = il; i < deg; i += 4)
        w[i*H1 + h] = expf(w[i*H1 + h] - m) * inv;
}

// ---------------------------------------------------------------------------
// Aggregation layer 1: warp per (node, relation), float4 channel gathers,
// unroll-4 for MLP. 8 warps (nodes) per block.
// ---------------------------------------------------------------------------
__global__ void k_agg1() {
    int e = blockIdx.y;
    int n = blockIdx.x * 8 + (threadIdx.x >> 5);
    if (n >= NN) return;
    int l = threadIdx.x & 31;          // lane: channels 4l..4l+3
    int h = l >> 2;                    // head of these channels

    int off = g_offsets[e*(NN+1) + n];
    int deg = g_offsets[e*(NN+1) + n + 1] - off;
    float4* out = reinterpret_cast<float4*>(g_out1 + (long)(e*NN + n) * C1);
    if (deg == 0) { out[l] = make_float4(0.f,0.f,0.f,0.f); return; }

    const int*    sr = g_srcs + e*NE + off;
    const float*  w  = g_w1 + (long)(e*NE + off) * H1;
    const float4* hs = reinterpret_cast<const float4*>(g_h1 + c_SRC[e]*NN*C1);

    float4 acc = make_float4(0.f,0.f,0.f,0.f);
    int i = 0;
    for (; i + 4 <= deg; i += 4) {
        int r0 = sr[i], r1 = sr[i+1], r2 = sr[i+2], r3 = sr[i+3];
        float w0 = w[(i+0)*H1 + h], w1 = w[(i+1)*H1 + h];
        float w2 = w[(i+2)*H1 + h], w3 = w[(i+3)*H1 + h];
        float4 v0 = hs[r0*32 + l], v1 = hs[r1*32 + l];
        float4 v2 = hs[r2*32 + l], v3 = hs[r3*32 + l];
        acc.x += w0*v0.x + w1*v1.x + w2*v2.x + w3*v3.x;
        acc.y += w0*v0.y + w1*v1.y + w2*v2.y + w3*v3.y;
        acc.z += w0*v0.z + w1*v1.z + w2*v2.z + w3*v3.z;
        acc.w += w0*v0.w + w1*v1.w + w2*v2.w + w3*v3.w;
    }
    for (; i < deg; i++) {
        int r = sr[i];
        float wv = w[i*H1 + h];
        float4 v = hs[r*32 + l];
        acc.x += wv*v.x; acc.y += wv*v.y; acc.z += wv*v.z; acc.w += wv*v.w;
    }
    out[l] = make_float4(fmaxf(acc.x,0.f), fmaxf(acc.y,0.f),
                         fmaxf(acc.z,0.f), fmaxf(acc.w,0.f));
}

// ---------------------------------------------------------------------------
// Semantic score + group softmax (tiny)
// ---------------------------------------------------------------------------
__global__ void k_score1(const float* __restrict__ q) {
    __shared__ float red[128];
    __shared__ float sc[NR];
    int t = threadIdx.x;
    for (int e = 0; e < NR; e++) {
        float p = q[t] * g_colsum1[e*C1 + t];
        red[t] = p; __syncthreads();
        for (int s = 64; s > 0; s >>= 1) {
            if (t < s) red[t] += red[t + s];
            __syncthreads();
        }
        if (t == 0) sc[e] = red[0] / (float)NN;
        __syncthreads();
    }
    if (t < NT) {
        int b = c_GRPOFF[t], e2 = c_GRPOFF[t+1];
        float m = -1e30f;
        for (int g = b; g < e2; g++) m = fmaxf(m, sc[c_GRP[g]]);
        float ssum = 0.f;
        for (int g = b; g < e2; g++) ssum += expf(sc[c_GRP[g]] - m);
        for (int g = b; g < e2; g++)
            g_sattn1[c_GRP[g]] = expf(sc[c_GRP[g]] - m) / ssum;
    }
}

__global__ void k_score2(const float* __restrict__ q) {
    __shared__ float red[128];
    __shared__ float sc[NR];
    int t = threadIdx.x;
    for (int e = 0; e < NR; e++) {
        float p = (t < C2) ? q[t] * g_colsum2[e*C2 + t] : 0.f;
        red[t] = p; __syncthreads();
        for (int s = 64; s > 0; s >>= 1) {
            if (t < s) red[t] += red[t + s];
            __syncthreads();
        }
        if (t == 0) sc[e] = red[0] / (float)NN;
        __syncthreads();
    }
    if (t < NT) {
        int b = c_GRPOFF[t], e2 = c_GRPOFF[t+1];
        float m = -1e30f;
        for (int g = b; g < e2; g++) m = fmaxf(m, sc[c_GRP[g]]);
        float ssum = 0.f;
        for (int g = b; g < e2; g++) ssum += expf(sc[c_GRP[g]] - m);
        for (int g = b; g < e2; g++)
            g_sattn2[c_GRP[g]] = expf(sc[c_GRP[g]] - m) / ssum;
    }
}

// ---------------------------------------------------------------------------
// Fuse relations per dst type (layer1) + elu -> x2
// ---------------------------------------------------------------------------
__global__ void k_combine1() {
    long idx = (long)blockIdx.x * blockDim.x + threadIdx.x;
    if (idx >= (long)NT*NN*C1) return;
    int t  = (int)(idx / (NN*C1));
    int nc = (int)(idx - (long)t*NN*C1);
    float v = 0.f;
    for (int g = c_GRPOFF[t]; g < c_GRPOFF[t+1]; g++) {
        int e = c_GRP[g];
        v += g_sattn1[e] * g_out1[(long)e*NN*C1 + nc];
    }
    g_x2[idx] = v > 0.f ? v : expf(v) - 1.f;
}

// ---------------------------------------------------------------------------
// Layer 2 logits (H=1): warp per (relation, node)
// ---------------------------------------------------------------------------
__global__ void k_logits2(const float* __restrict__ att_src,
                          const float* __restrict__ att_dst)
{
    int e = blockIdx.y;
    int n = blockIdx.x * 8 + (threadIdx.x >> 5);
    if (n >= NN) return;
    int l = threadIdx.x & 31;
    float ps = g_h2[c_SRC[e]*NN*C2 + n*C2 + l] * att_src[e*C2 + l];
    float pd = g_h2[c_DST[e]*NN*C2 + n*C2 + l] * att_dst[e*C2 + l];
#pragma unroll
    for (int o = 16; o > 0; o >>= 1) {
        ps += __shfl_xor_sync(0xffffffffu, ps, o);
        pd += __shfl_xor_sync(0xffffffffu, pd, o);
    }
    if (l == 0) { g_asrc2[e*NN + n] = ps; g_adst2[e*NN + n] = pd; }
}

// ---------------------------------------------------------------------------
// Segment softmax, layer 2: warp per (relation, node), two-pass via w buffer.
// ---------------------------------------------------------------------------
__global__ void k_soft2() {
    int e = blockIdx.y;
    int n = blockIdx.x * 8 + (threadIdx.x >> 5);
    if (n >= NN) return;
    int l = threadIdx.x & 31;

    int off = g_offsets[e*(NN+1) + n];
    int deg = g_offsets[e*(NN+1) + n + 1] - off;
    if (deg == 0) return;

    const int*   sr  = g_srcs + e*NE + off;
    const float* asr = g_asrc2 + e*NN;
    float ad = g_adst2[e*NN + n];
    float* w = g_w2 + e*NE + off;

    float m = -1e30f, s = 0.f;
    for (int i = l; i < deg; i += 32) {
        float a = asr[sr[i]] + ad;
        a = a > 0.f ? a : 0.2f * a;
        w[i] = a;
        if (a > m) { s = s * expf(m - a) + 1.f; m = a; }
        else        s += expf(a - m);
    }
#pragma unroll
    for (int o = 1; o <= 16; o <<= 1) {
        float mo = __shfl_xor_sync(0xffffffffu, m, o);
        float so = __shfl_xor_sync(0xffffffffu, s, o);
        float mn = fmaxf(m, mo);
        s = s * expf(m - mn) + so * expf(mo - mn);
        m = mn;
    }
    float inv = 1.f / (s + 1e-16f);
    for (int i = l; i < deg; i += 32)
        w[i] = expf(w[i] - m) * inv;
}

// ---------------------------------------------------------------------------
// Aggregation layer 2: warp per (node, relation); 4 edges in flight
// (8 lanes x float4 per edge), shfl-reduce across edge groups.
// ---------------------------------------------------------------------------
__global__ void k_agg2() {
    int e = blockIdx.y;
    int n = blockIdx.x * 8 + (threadIdx.x >> 5);
    if (n >= NN) return;
    int l = threadIdx.x & 31;
    int g = l >> 3;                    // edge group 0..3
    int q = l & 7;                     // channel quad 0..7

    int off = g_offsets[e*(NN+1) + n];
    int deg = g_offsets[e*(NN+1) + n + 1] - off;
    float4* out = reinterpret_cast<float4*>(g_out2 + (long)(e*NN + n) * C2);
    if (deg == 0) { if (l < 8) out[q] = make_float4(0.f,0.f,0.f,0.f); return; }

    const int*    sr = g_srcs + e*NE + off;
    const float*  w  = g_w2 + e*NE + off;
    const float4* hs = reinterpret_cast<const float4*>(g_h2 + c_SRC[e]*NN*C2);

    float4 acc = make_float4(0.f,0.f,0.f,0.f);
    for (int i = g; i < deg; i += 4) {
        int r = sr[i];
        float wv = w[i];
        float4 v = hs[r*8 + q];
        acc.x += wv*v.x; acc.y += wv*v.y; acc.z += wv*v.z; acc.w += wv*v.w;
    }
#pragma unroll
    for (int o = 8; o <= 16; o <<= 1) {
        acc.x += __shfl_xor_sync(0xffffffffu, acc.x, o);
        acc.y += __shfl_xor_sync(0xffffffffu, acc.y, o);
        acc.z += __shfl_xor_sync(0xffffffffu, acc.z, o);
        acc.w += __shfl_xor_sync(0xffffffffu, acc.w, o);
    }
    if (l < 8)
        out[q] = make_float4(fmaxf(acc.x,0.f), fmaxf(acc.y,0.f),
                             fmaxf(acc.z,0.f), fmaxf(acc.w,0.f));
}

// ---------------------------------------------------------------------------
// Fuse relations layer 2 + final per-node channel softmax -> d_out
// ---------------------------------------------------------------------------
__global__ void k_combine2(float* __restrict__ out) {
    int g = blockIdx.x * 8 + (threadIdx.x >> 5);
    if (g >= NT*NN) return;
    int t = g / NN, n = g - t*NN;
    int c = threadIdx.x & 31;
    float v = 0.f;
    for (int gi = c_GRPOFF[t]; gi < c_GRPOFF[t+1]; gi++) {
        int e = c_GRP[gi];
        v += g_sattn2[e] * g_out2[(long)(e*NN + n)*C2 + c];
    }
    float m = v;
#pragma unroll
    for (int o = 16; o > 0; o >>= 1)
        m = fmaxf(m, __shfl_xor_sync(0xffffffffu, m, o));
    float ex = expf(v - m);
    float s = ex;
#pragma unroll
    for (int o = 16; o > 0; o >>= 1)
        s += __shfl_xor_sync(0xffffffffu, s, o);
    out[(long)g*C2 + c] = ex / s;
}

// ---------------------------------------------------------------------------
// Host launcher
// ---------------------------------------------------------------------------
extern "C" void kernel_launch(void* const* d_in, const int* in_sizes, int n_in,
                              void* d_out, int out_size)
{
    const float* x[4] = {(const float*)d_in[0], (const float*)d_in[1],
                         (const float*)d_in[2], (const float*)d_in[3]};
    const int*   edges    = (const int*)  d_in[4];
    const float* proj1_W  = (const float*)d_in[5];
    const float* proj1_b  = (const float*)d_in[6];
    const float* att1_src = (const float*)d_in[7];
    const float* att1_dst = (const float*)d_in[8];
    const float* k1_W     = (const float*)d_in[9];
    const float* k1_b     = (const float*)d_in[10];
    const float* q1       = (const float*)d_in[11];
    const float* proj2_W  = (const float*)d_in[12];
    const float* proj2_b  = (const float*)d_in[13];
    const float* att2_src = (const float*)d_in[14];
    const float* att2_dst = (const float*)d_in[15];
    const float* k2_W     = (const float*)d_in[16];
    const float* k2_b     = (const float*)d_in[17];
    const float* q2       = (const float*)d_in[18];
    float* out = (float*)d_out;

    float *h1p, *x2p, *h2p, *out1p, *out2p, *cs1p, *cs2p;
    cudaGetSymbolAddress((void**)&h1p,   g_h1);
    cudaGetSymbolAddress((void**)&x2p,   g_x2);
    cudaGetSymbolAddress((void**)&h2p,   g_h2);
    cudaGetSymbolAddress((void**)&out1p, g_out1);
    cudaGetSymbolAddress((void**)&out2p, g_out2);
    cudaGetSymbolAddress((void**)&cs1p,  g_colsum1);
    cudaGetSymbolAddress((void**)&cs2p,  g_colsum2);

    const int MT = (NN + 127) / 128;   // 235 row tiles

    // launch idx 0-2: setup; idx 3 = batched proj1 GEMM (profiled by ncu)
    k_zero <<<(NR*NN + 255)/256, 256>>>();
    k_count<<<(NR*NE + 255)/256, 256>>>(edges);
    k_scan <<<NR, 1024>>>();

    // ---- layer 1 projections, batched z=4 (PROFILED) ----
    k_gemm<0><<<dim3(MT, 1, NT), 256>>>(
        x[0], x[1], x[2], x[3],
        proj1_W, proj1_b, h1p, NN, C1, IN1,
        0, (long)IN1*C1, C1, (long)NN*C1, nullptr, 0);

    k_fill <<<(NR*NE + 255)/256, 256>>>(edges);

    k_logits1<<<dim3((NN + 7)/8, NR), 256>>>(att1_src, att1_dst);
    k_soft1  <<<dim3((NN + 7)/8, NR), 256>>>();
    k_agg1   <<<dim3((NN + 7)/8, NR), 256>>>();

    k_gemm<1><<<dim3(MT, 1, NR), 256>>>(
        out1p, nullptr, nullptr, nullptr,
        k1_W, k1_b, nullptr, NN, C1, C1,
        (long)NN*C1, 0, 0, 0, cs1p, C1);
    k_score1<<<1, 128>>>(q1);
    k_combine1<<<((long)NT*NN*C1 + 255)/256, 256>>>();

    // ---- layer 2 projections, batched z=4 ----
    k_gemm<0><<<dim3(MT, 1, NT), 256>>>(
        x2p, nullptr, nullptr, nullptr,
        proj2_W, proj2_b, h2p, NN, C2, C1,
        (long)NN*C1, (long)C1*C2, C2, (long)NN*C2, nullptr, 0);

    k_logits2<<<dim3((NN + 7)/8, NR), 256>>>(att2_src, att2_dst);
    k_soft2  <<<dim3((NN + 7)/8, NR), 256>>>();
    k_agg2   <<<dim3((NN + 7)/8, NR), 256>>>();

    k_gemm<1><<<dim3(MT, 1, NR), 256>>>(
        out2p, nullptr, nullptr, nullptr,
        k2_W, k2_b, nullptr, NN, C2, C2,
        (long)NN*C2, 0, 0, 0, cs2p, C2);
    k_score2<<<1, 128>>>(q2);

    k_combine2<<<(NT*NN + 7)/8, 256>>>(out);
}